// round 1
// baseline (speedup 1.0000x reference)
#include <cuda_runtime.h>
#include <math.h>

#define WSZ 8
#define NHEAD 4
#define DIM 128
#define NTOK 64
#define HD 32
#define BATCH 32
#define HW 64
#define LSEQ 4096
#define PAD 129
#define SPAD 65
#define RPE_HID 512

__device__ float g_bias[NHEAD * NTOK * NTOK];
__device__ float g_ybuf[(size_t)BATCH * LSEQ * DIM];

// ---------------- Kernel 1: continuous RPE bias table ----------------
__global__ void bias_kernel(const float* __restrict__ w1, const float* __restrict__ b1,
                            const float* __restrict__ w2) {
    __shared__ float ttab[225][NHEAD];
    int tid = threadIdx.x;
    if (tid < 225) {
        int i = tid / 15, j = tid % 15;
        float v0 = (float)(i - 7) / 7.0f * 8.0f;
        float v1 = (float)(j - 7) / 7.0f * 8.0f;
        float inv_l8 = 1.0f / log2f(8.0f);
        float s0 = (v0 > 0.f) ? 1.f : ((v0 < 0.f) ? -1.f : 0.f);
        float s1 = (v1 > 0.f) ? 1.f : ((v1 < 0.f) ? -1.f : 0.f);
        float x0 = s0 * log2f(fabsf(v0) + 1.0f) * inv_l8;
        float x1 = s1 * log2f(fabsf(v1) + 1.0f) * inv_l8;
        float acc0 = 0.f, acc1 = 0.f, acc2 = 0.f, acc3 = 0.f;
        for (int h = 0; h < RPE_HID; h++) {
            float hid = x0 * w1[2 * h] + x1 * w1[2 * h + 1] + b1[h];
            hid = fmaxf(hid, 0.f);
            acc0 += hid * w2[0 * RPE_HID + h];
            acc1 += hid * w2[1 * RPE_HID + h];
            acc2 += hid * w2[2 * RPE_HID + h];
            acc3 += hid * w2[3 * RPE_HID + h];
        }
        ttab[tid][0] = acc0; ttab[tid][1] = acc1;
        ttab[tid][2] = acc2; ttab[tid][3] = acc3;
    }
    __syncthreads();
    for (int e = tid; e < NHEAD * NTOK * NTOK; e += blockDim.x) {
        int h = e >> 12;
        int rem = e & 4095;
        int i = rem >> 6, j = rem & 63;
        int yi = i >> 3, xi = i & 7, yj = j >> 3, xj = j & 7;
        int idx = (yi - yj + 7) * 15 + (xi - xj + 7);
        g_bias[e] = ttab[idx][h];
    }
}

// ---------------- Kernel 2: fused shifted-window attention + LN1 + residual ----------------
// smem layout (floats):
//   xw  [64][129]   input window, later reused as attn-output (PV result)
//   wb  [128][129]  weight staging (qkv chunks, then proj_w)
//   qb,kb,vb [64][129]  (vb later reused as proj output)
//   sb  [64][65]    per-head scores / exp(P)
//   rsum[64], mu[64], rstd[64], regid[64]
__global__ __launch_bounds__(256) void attn_kernel(
    const float* __restrict__ x, const float* __restrict__ qkv_w, const float* __restrict__ qkv_b,
    const float* __restrict__ proj_w, const float* __restrict__ proj_b,
    const float* __restrict__ n1w, const float* __restrict__ n1b)
{
    extern __shared__ float sm[];
    float* xw = sm;
    float* wb = xw + NTOK * PAD;
    float* qb = wb + DIM * PAD;
    float* kb = qb + NTOK * PAD;
    float* vb = kb + NTOK * PAD;
    float* sb = vb + NTOK * PAD;
    float* rsum = sb + NTOK * SPAD;
    float* mu = rsum + 64;
    float* rstd = mu + 64;
    int* regid = (int*)(rstd + 64);

    int tid = threadIdx.x;
    int bx = blockIdx.x;
    int bimg = bx >> 6;
    int wh = (bx >> 3) & 7, ww = bx & 7;
    const float* xbase = x + (size_t)bimg * (LSEQ * DIM);

    // load window (applies -SS roll; source pos == final writeback pos)
    #pragma unroll
    for (int it = 0; it < 8; it++) {
        int e4 = tid + 256 * it;          // 2048 float4
        int t = e4 >> 5;
        int c = (e4 & 31) << 2;
        int ti = t >> 3, tj = t & 7;
        int hh = (wh * 8 + ti + 4) & 63;
        int wwp = (ww * 8 + tj + 4) & 63;
        float4 v = *(const float4*)(xbase + (size_t)((hh << 6) + wwp) * DIM + c);
        float* d = xw + t * PAD + c;
        d[0] = v.x; d[1] = v.y; d[2] = v.z; d[3] = v.w;
    }
    if (tid < 64) {
        int ti = tid >> 3, tj = tid & 7;
        int ah = wh * 8 + ti, aw = ww * 8 + tj;
        int rh = ah < 56 ? 0 : (ah < 60 ? 1 : 2);
        int rw = aw < 56 ? 0 : (aw < 60 ? 1 : 2);
        regid[tid] = rh * 3 + rw;
    }
    __syncthreads();

    int ty = tid >> 4, tx = tid & 15;

    // ---- QKV: 3 chunks of 128 outputs ----
    for (int cidx = 0; cidx < 3; cidx++) {
        const float* wsrc = qkv_w + cidx * DIM * DIM;
        #pragma unroll
        for (int it = 0; it < 16; it++) {
            int e4 = tid + 256 * it;      // 4096 float4
            int r = e4 >> 5;
            int c = (e4 & 31) << 2;
            float4 v = *(const float4*)(wsrc + r * DIM + c);
            float* d = wb + r * PAD + c;
            d[0] = v.x; d[1] = v.y; d[2] = v.z; d[3] = v.w;
        }
        __syncthreads();
        float acc[4][8];
        #pragma unroll
        for (int i = 0; i < 4; i++)
            #pragma unroll
            for (int j = 0; j < 8; j++) acc[i][j] = 0.f;
        #pragma unroll 4
        for (int k = 0; k < DIM; k++) {
            float a[4], bv[8];
            #pragma unroll
            for (int i = 0; i < 4; i++) a[i] = xw[(ty + 16 * i) * PAD + k];
            #pragma unroll
            for (int j = 0; j < 8; j++) bv[j] = wb[(tx + 16 * j) * PAD + k];
            #pragma unroll
            for (int i = 0; i < 4; i++)
                #pragma unroll
                for (int j = 0; j < 8; j++) acc[i][j] += a[i] * bv[j];
        }
        float* dst = (cidx == 0) ? qb : ((cidx == 1) ? kb : vb);
        #pragma unroll
        for (int i = 0; i < 4; i++) {
            int t = ty + 16 * i;
            #pragma unroll
            for (int j = 0; j < 8; j++) {
                int o = tx + 16 * j;
                dst[t * PAD + o] = acc[i][j] + qkv_b[cidx * DIM + o];
            }
        }
        __syncthreads();
    }

    // ---- per-head attention ----
    const float scale = 0.17677669529663687f;  // 32^-0.5
    for (int h = 0; h < NHEAD; h++) {
        int hoff = h * HD;
        // scores S = (q*scale) k^T + bias + mask
        float sacc[4][4];
        #pragma unroll
        for (int i = 0; i < 4; i++)
            #pragma unroll
            for (int j = 0; j < 4; j++) sacc[i][j] = 0.f;
        #pragma unroll 4
        for (int k = 0; k < HD; k++) {
            float a[4], bv[4];
            #pragma unroll
            for (int i = 0; i < 4; i++) a[i] = qb[(ty + 16 * i) * PAD + hoff + k];
            #pragma unroll
            for (int j = 0; j < 4; j++) bv[j] = kb[(tx + 16 * j) * PAD + hoff + k];
            #pragma unroll
            for (int i = 0; i < 4; i++)
                #pragma unroll
                for (int j = 0; j < 4; j++) sacc[i][j] += a[i] * bv[j];
        }
        #pragma unroll
        for (int i = 0; i < 4; i++) {
            int iT = ty + 16 * i;
            int ri = regid[iT];
            #pragma unroll
            for (int j = 0; j < 4; j++) {
                int jT = tx + 16 * j;
                float m = (ri != regid[jT]) ? -100.f : 0.f;
                sb[iT * SPAD + jT] = sacc[i][j] * scale + g_bias[(h * 64 + iT) * 64 + jT] + m;
            }
        }
        __syncthreads();
        // softmax (store unnormalized exp; reciprocal row sums)
        if (tid < 64) {
            float mx = -1e30f;
            for (int j = 0; j < 64; j++) mx = fmaxf(mx, sb[tid * SPAD + j]);
            float s = 0.f;
            for (int j = 0; j < 64; j++) {
                float e = __expf(sb[tid * SPAD + j] - mx);
                sb[tid * SPAD + j] = e;
                s += e;
            }
            rsum[tid] = 1.0f / s;
        }
        __syncthreads();
        // out_h = P @ v_h  (divide by rowsum in epilogue); write into xw
        float oacc[4][2];
        #pragma unroll
        for (int i = 0; i < 4; i++) { oacc[i][0] = 0.f; oacc[i][1] = 0.f; }
        #pragma unroll 4
        for (int k = 0; k < 64; k++) {
            float a[4];
            #pragma unroll
            for (int i = 0; i < 4; i++) a[i] = sb[(ty + 16 * i) * SPAD + k];
            float b0 = vb[k * PAD + hoff + tx];
            float b1 = vb[k * PAD + hoff + tx + 16];
            #pragma unroll
            for (int i = 0; i < 4; i++) { oacc[i][0] += a[i] * b0; oacc[i][1] += a[i] * b1; }
        }
        #pragma unroll
        for (int i = 0; i < 4; i++) {
            int t = ty + 16 * i;
            float rs = rsum[t];
            xw[t * PAD + hoff + tx] = oacc[i][0] * rs;
            xw[t * PAD + hoff + tx + 16] = oacc[i][1] * rs;
        }
        __syncthreads();
    }

    // ---- proj GEMM ----
    #pragma unroll
    for (int it = 0; it < 16; it++) {
        int e4 = tid + 256 * it;
        int r = e4 >> 5;
        int c = (e4 & 31) << 2;
        float4 v = *(const float4*)(proj_w + r * DIM + c);
        float* d = wb + r * PAD + c;
        d[0] = v.x; d[1] = v.y; d[2] = v.z; d[3] = v.w;
    }
    __syncthreads();
    {
        float acc[4][8];
        #pragma unroll
        for (int i = 0; i < 4; i++)
            #pragma unroll
            for (int j = 0; j < 8; j++) acc[i][j] = 0.f;
        #pragma unroll 4
        for (int k = 0; k < DIM; k++) {
            float a[4], bv[8];
            #pragma unroll
            for (int i = 0; i < 4; i++) a[i] = xw[(ty + 16 * i) * PAD + k];
            #pragma unroll
            for (int j = 0; j < 8; j++) bv[j] = wb[(tx + 16 * j) * PAD + k];
            #pragma unroll
            for (int i = 0; i < 4; i++)
                #pragma unroll
                for (int j = 0; j < 8; j++) acc[i][j] += a[i] * bv[j];
        }
        #pragma unroll
        for (int i = 0; i < 4; i++) {
            int t = ty + 16 * i;
            #pragma unroll
            for (int j = 0; j < 8; j++) {
                int o = tx + 16 * j;
                vb[t * PAD + o] = acc[i][j] + proj_b[o];   // vb reused as proj output
            }
        }
    }
    __syncthreads();

    // ---- LN1 stats (two-pass) ----
    if (tid < 64) {
        float s = 0.f;
        for (int c = 0; c < DIM; c++) s += vb[tid * PAD + c];
        float m = s * (1.0f / DIM);
        float v = 0.f;
        for (int c = 0; c < DIM; c++) {
            float d = vb[tid * PAD + c] - m;
            v += d * d;
        }
        mu[tid] = m;
        rstd[tid] = rsqrtf(v * (1.0f / DIM) + 1e-5f);
    }
    __syncthreads();

    // ---- y = x + LN(proj) at the (same) unshifted position ----
    float* yb = g_ybuf + (size_t)bimg * (LSEQ * DIM);
    #pragma unroll
    for (int it = 0; it < 8; it++) {
        int e4 = tid + 256 * it;
        int t = e4 >> 5;
        int c = (e4 & 31) << 2;
        int ti = t >> 3, tj = t & 7;
        int hh = (wh * 8 + ti + 4) & 63;
        int wwp = (ww * 8 + tj + 4) & 63;
        size_t goff = (size_t)((hh << 6) + wwp) * DIM + c;
        float4 xv = *(const float4*)(xbase + goff);
        float m = mu[t], r = rstd[t];
        float4 o;
        o.x = xv.x + (vb[t * PAD + c + 0] - m) * r * n1w[c + 0] + n1b[c + 0];
        o.y = xv.y + (vb[t * PAD + c + 1] - m) * r * n1w[c + 1] + n1b[c + 1];
        o.z = xv.z + (vb[t * PAD + c + 2] - m) * r * n1w[c + 2] + n1b[c + 2];
        o.w = xv.w + (vb[t * PAD + c + 3] - m) * r * n1w[c + 3] + n1b[c + 3];
        *(float4*)(yb + goff) = o;
    }
}

// ---------------- Kernel 3: fused MLP + LN2 + residual ----------------
__global__ __launch_bounds__(256) void mlp_kernel(
    const float* __restrict__ fc1w, const float* __restrict__ fc1b,
    const float* __restrict__ fc2w, const float* __restrict__ fc2b,
    const float* __restrict__ n2w, const float* __restrict__ n2b,
    float* __restrict__ out)
{
    extern __shared__ float sm[];
    float* yt = sm;                 // 64*129
    float* wb = yt + NTOK * PAD;    // 128*129
    float* h1 = wb + DIM * PAD;     // 64*129 (later h2)
    float* mu = h1 + NTOK * PAD;
    float* rstd = mu + 64;

    int tid = threadIdx.x;
    size_t tok0 = (size_t)blockIdx.x * 64;
    const float* ysrc = g_ybuf + tok0 * DIM;

    #pragma unroll
    for (int it = 0; it < 8; it++) {
        int e4 = tid + 256 * it;
        int t = e4 >> 5;
        int c = (e4 & 31) << 2;
        float4 v = *(const float4*)(ysrc + t * DIM + c);
        float* d = yt + t * PAD + c;
        d[0] = v.x; d[1] = v.y; d[2] = v.z; d[3] = v.w;
    }
    __syncthreads();

    int ty = tid >> 4, tx = tid & 15;
    float acc[4][8];   // h2 accumulators
    #pragma unroll
    for (int i = 0; i < 4; i++)
        #pragma unroll
        for (int j = 0; j < 8; j++) acc[i][j] = 0.f;

    for (int hc = 0; hc < 4; hc++) {
        // fc1 chunk (rows hc*128..+128)
        const float* w1 = fc1w + (size_t)hc * 128 * DIM;
        #pragma unroll
        for (int it = 0; it < 16; it++) {
            int e4 = tid + 256 * it;
            int r = e4 >> 5;
            int c = (e4 & 31) << 2;
            float4 v = *(const float4*)(w1 + r * DIM + c);
            float* d = wb + r * PAD + c;
            d[0] = v.x; d[1] = v.y; d[2] = v.z; d[3] = v.w;
        }
        __syncthreads();
        // h1c = gelu(yt @ w1^T + b1)
        float hacc[4][8];
        #pragma unroll
        for (int i = 0; i < 4; i++)
            #pragma unroll
            for (int j = 0; j < 8; j++) hacc[i][j] = 0.f;
        #pragma unroll 4
        for (int k = 0; k < DIM; k++) {
            float a[4], bv[8];
            #pragma unroll
            for (int i = 0; i < 4; i++) a[i] = yt[(ty + 16 * i) * PAD + k];
            #pragma unroll
            for (int j = 0; j < 8; j++) bv[j] = wb[(tx + 16 * j) * PAD + k];
            #pragma unroll
            for (int i = 0; i < 4; i++)
                #pragma unroll
                for (int j = 0; j < 8; j++) hacc[i][j] += a[i] * bv[j];
        }
        #pragma unroll
        for (int i = 0; i < 4; i++) {
            int t = ty + 16 * i;
            #pragma unroll
            for (int j = 0; j < 8; j++) {
                int o = tx + 16 * j;
                float v = hacc[i][j] + fc1b[hc * 128 + o];
                float g = 0.5f * v * (1.0f + erff(v * 0.70710678118654752f));
                h1[t * PAD + o] = g;
            }
        }
        __syncthreads();
        // fc2 chunk: wb[c][hh] = fc2w[c][hc*128+hh]
        #pragma unroll
        for (int it = 0; it < 16; it++) {
            int e4 = tid + 256 * it;
            int c = e4 >> 5;
            int hh = (e4 & 31) << 2;
            float4 v = *(const float4*)(fc2w + (size_t)c * 512 + hc * 128 + hh);
            float* d = wb + c * PAD + hh;
            d[0] = v.x; d[1] = v.y; d[2] = v.z; d[3] = v.w;
        }
        __syncthreads();
        // h2 += h1c @ fc2chunk^T
        #pragma unroll 4
        for (int k = 0; k < DIM; k++) {
            float a[4], bv[8];
            #pragma unroll
            for (int i = 0; i < 4; i++) a[i] = h1[(ty + 16 * i) * PAD + k];
            #pragma unroll
            for (int j = 0; j < 8; j++) bv[j] = wb[(tx + 16 * j) * PAD + k];
            #pragma unroll
            for (int i = 0; i < 4; i++)
                #pragma unroll
                for (int j = 0; j < 8; j++) acc[i][j] += a[i] * bv[j];
        }
        __syncthreads();
    }

    // write h2 (+bias) into h1 buffer
    #pragma unroll
    for (int i = 0; i < 4; i++) {
        int t = ty + 16 * i;
        #pragma unroll
        for (int j = 0; j < 8; j++) {
            int o = tx + 16 * j;
            h1[t * PAD + o] = acc[i][j] + fc2b[o];
        }
    }
    __syncthreads();
    if (tid < 64) {
        float s = 0.f;
        for (int c = 0; c < DIM; c++) s += h1[tid * PAD + c];
        float m = s * (1.0f / DIM);
        float v = 0.f;
        for (int c = 0; c < DIM; c++) {
            float d = h1[tid * PAD + c] - m;
            v += d * d;
        }
        mu[tid] = m;
        rstd[tid] = rsqrtf(v * (1.0f / DIM) + 1e-5f);
    }
    __syncthreads();
    float* od = out + tok0 * DIM;
    #pragma unroll
    for (int it = 0; it < 8; it++) {
        int e4 = tid + 256 * it;
        int t = e4 >> 5;
        int c = (e4 & 31) << 2;
        float m = mu[t], r = rstd[t];
        float4 o;
        o.x = yt[t * PAD + c + 0] + (h1[t * PAD + c + 0] - m) * r * n2w[c + 0] + n2b[c + 0];
        o.y = yt[t * PAD + c + 1] + (h1[t * PAD + c + 1] - m) * r * n2w[c + 1] + n2b[c + 1];
        o.z = yt[t * PAD + c + 2] + (h1[t * PAD + c + 2] - m) * r * n2w[c + 2] + n2b[c + 2];
        o.w = yt[t * PAD + c + 3] + (h1[t * PAD + c + 3] - m) * r * n2w[c + 3] + n2b[c + 3];
        *(float4*)(od + t * DIM + c) = o;
    }
}

static const int ATTN_SMEM = (4 * NTOK * PAD + DIM * PAD + NTOK * SPAD + 3 * 64) * 4 + 64 * 4;
static const int MLP_SMEM  = (2 * NTOK * PAD + DIM * PAD + 2 * 64) * 4;

extern "C" void kernel_launch(void* const* d_in, const int* in_sizes, int n_in,
                              void* d_out, int out_size) {
    const float* x      = (const float*)d_in[0];
    const float* qkv_w  = (const float*)d_in[1];
    const float* qkv_b  = (const float*)d_in[2];
    const float* proj_w = (const float*)d_in[3];
    const float* proj_b = (const float*)d_in[4];
    const float* rpe_w1 = (const float*)d_in[5];
    const float* rpe_b1 = (const float*)d_in[6];
    const float* rpe_w2 = (const float*)d_in[7];
    const float* n1w    = (const float*)d_in[8];
    const float* n1b    = (const float*)d_in[9];
    const float* fc1w   = (const float*)d_in[10];
    const float* fc1b   = (const float*)d_in[11];
    const float* fc2w   = (const float*)d_in[12];
    const float* fc2b   = (const float*)d_in[13];
    const float* n2w    = (const float*)d_in[14];
    const float* n2b    = (const float*)d_in[15];
    float* out = (float*)d_out;

    cudaFuncSetAttribute(attn_kernel, cudaFuncAttributeMaxDynamicSharedMemorySize, ATTN_SMEM);
    cudaFuncSetAttribute(mlp_kernel,  cudaFuncAttributeMaxDynamicSharedMemorySize, MLP_SMEM);

    bias_kernel<<<1, 256>>>(rpe_w1, rpe_b1, rpe_w2);
    attn_kernel<<<2048, 256, ATTN_SMEM>>>(x, qkv_w, qkv_b, proj_w, proj_b, n1w, n1b);
    mlp_kernel<<<2048, 256, MLP_SMEM>>>(fc1w, fc1b, fc2w, fc2b, n2w, n2b, out);
}